// round 17
// baseline (speedup 1.0000x reference)
#include <cuda_runtime.h>
#include <stdint.h>

// BATCH=128, BUFFER_SIZE=16, IMG = 128*128*3 = 49152 floats = 12288 float4
// out[m] = combined[m/16 + 1 + m%16], combined = concat(buffer, inputs)
//
// Gather form (beats scatter: R7/R14). Grid: y = output image m (0..2047),
// x = chunk (0..5) of 2048 float4. 256 threads, 8 float4/thread at stride 256.
//
// R15 lesson: __ldcg with all 8 loads live -> 40 regs -> occ 63.7%. Fix:
// depth-4 software pipeline (load a0..a3; then {store a_i; load a_{i+4}}),
// capping live payload at 4-5 float4 (~regs <=32 -> 8 CTAs/SM) while keeping
// MLP>=4 sustained. Loads __ldcg (reuse is cross-SM, lives in L2);
// stores __stcs (output never re-read).

#define KBUF 16
#define IMG4 12288
#define CHUNK4 2048   // float4 per block (6 chunks per image)

__global__ __launch_bounds__(256, 8) void image_buffer_gather(
    const float4* __restrict__ inputs,   // [128, IMG4]
    const float4* __restrict__ buffer,   // [16,  IMG4]
    float4* __restrict__ out)            // [2048, IMG4]
{
    const int m = blockIdx.y;            // output image index, 0..2047
    const int i = m >> 4;
    const int k = m & 15;
    const int j = i + 1 + k;             // combined index, 1..143 (block-uniform)

    const float4* __restrict__ srcimg = (j < KBUF)
        ? (buffer + j * IMG4)
        : (inputs + (j - KBUF) * IMG4);

    const int base = blockIdx.x * CHUNK4 + threadIdx.x;
    const float4* __restrict__ src = srcimg + base;
    float4* __restrict__ dst = out + (int64_t)m * IMG4 + base;

    // Depth-4 pipelined copy of 8 float4 (stride 256 between elements).
    float4 a0 = __ldcg(src + 0 * 256);
    float4 a1 = __ldcg(src + 1 * 256);
    float4 a2 = __ldcg(src + 2 * 256);
    float4 a3 = __ldcg(src + 3 * 256);

    __stcs(dst + 0 * 256, a0);  a0 = __ldcg(src + 4 * 256);
    __stcs(dst + 1 * 256, a1);  a1 = __ldcg(src + 5 * 256);
    __stcs(dst + 2 * 256, a2);  a2 = __ldcg(src + 6 * 256);
    __stcs(dst + 3 * 256, a3);  a3 = __ldcg(src + 7 * 256);

    __stcs(dst + 4 * 256, a0);
    __stcs(dst + 5 * 256, a1);
    __stcs(dst + 6 * 256, a2);
    __stcs(dst + 7 * 256, a3);
}

extern "C" void kernel_launch(void* const* d_in, const int* in_sizes, int n_in,
                              void* d_out, int out_size) {
    const float4* inputs = (const float4*)d_in[0];
    const float4* buffer = (const float4*)d_in[1];
    float4* out = (float4*)d_out;

    dim3 grid(6, 2048);   // 6 chunks x 2048 output images = 12288 blocks
    image_buffer_gather<<<grid, 256>>>(inputs, buffer, out);
}